// round 3
// baseline (speedup 1.0000x reference)
#include <cuda_runtime.h>
#include <math.h>

#define NN   100000
#define EE   300000
#define DINF 128
#define HH   512
#define GG   4096
#define OUTC 256
#define SLOPE 0.01f
#define EPS   1e-5f

// -------- scratch (device globals: allocation-free, 256B aligned) --------
__device__ __align__(256) float    g_deg[NN];
__device__ __align__(256) float    g_dinv[NN];
__device__ __align__(256) float    g_selfc[NN];
__device__ __align__(256) float    g_norm[EE];
__device__ __align__(256) float    g_buf1[(size_t)NN * HH];   // 204.8 MB
__device__ __align__(256) float    g_buf2[(size_t)NN * HH];   // 204.8 MB
__device__ __align__(256) unsigned g_keys[(size_t)GG * HH];
__device__ __align__(256) float    g_pooled[(size_t)GG * HH];
__device__ __align__(256) float    g_stats[4 * HH];           // sum1, sumsq1, sum2, sumsq2
__device__ __align__(256) float    g_bna[HH];
__device__ __align__(256) float    g_bnc[HH];

// -------- init: deg=2 (improved self-loop), pool keys=0, stats=0 --------
__global__ void init_kernel() {
    int i = blockIdx.x * blockDim.x + threadIdx.x;
    if (i < NN) g_deg[i] = 2.0f;
    if (i < GG * HH) g_keys[i] = 0u;
    if (i < 4 * HH) g_stats[i] = 0.0f;
}

__global__ void count_deg_kernel(const int* __restrict__ ecol) {
    int e = blockIdx.x * blockDim.x + threadIdx.x;
    if (e < EE) atomicAdd(&g_deg[ecol[e]], 1.0f);
}

__global__ void dinv_kernel() {
    int i = blockIdx.x * blockDim.x + threadIdx.x;
    if (i < NN) {
        float d = g_deg[i];
        float di = rsqrtf(d);
        g_dinv[i] = di;
        g_selfc[i] = 2.0f * di * di;   // SELF_W * dinv^2
    }
}

__global__ void edge_norm_kernel(const int* __restrict__ erow,
                                 const int* __restrict__ ecol) {
    int e = blockIdx.x * blockDim.x + threadIdx.x;
    if (e < EE) g_norm[e] = g_dinv[erow[e]] * g_dinv[ecol[e]];
}

// -------- register-tiled SGEMM: C[M,N] = A[M,K] @ B[K,N] (+bias) --------
#define BM 128
#define BN 128
#define BK 8
#define TM 8
#define TN 8

__global__ __launch_bounds__(256)
void sgemm_kernel(const float* __restrict__ A, const float* __restrict__ B,
                  const float* __restrict__ bias, float* __restrict__ C,
                  int M, int N, int K) {
    __shared__ float As[BK][BM];
    __shared__ float Bs[BK][BN];
    int tid = threadIdx.x;
    int bm = blockIdx.y * BM;
    int bn = blockIdx.x * BN;
    int tcol = tid % 16;     // 16 threads across N
    int trow = tid / 16;     // 16 threads down M

    float acc[TM][TN];
#pragma unroll
    for (int i = 0; i < TM; i++)
#pragma unroll
        for (int j = 0; j < TN; j++) acc[i][j] = 0.0f;

    int aRow = tid >> 1;            // 0..127
    int aCol = (tid & 1) * 4;       // 0 or 4
    int bRow = tid >> 5;            // 0..7
    int bCol = (tid & 31) * 4;

    const float* Ablk = A + (long long)bm * K;

    for (int k0 = 0; k0 < K; k0 += BK) {
        float4 av;
        if (bm + aRow < M)
            av = *reinterpret_cast<const float4*>(Ablk + (long long)aRow * K + k0 + aCol);
        else
            av = make_float4(0.f, 0.f, 0.f, 0.f);
        As[aCol + 0][aRow] = av.x;
        As[aCol + 1][aRow] = av.y;
        As[aCol + 2][aRow] = av.z;
        As[aCol + 3][aRow] = av.w;

        float4 bv = *reinterpret_cast<const float4*>(B + (long long)(k0 + bRow) * N + bn + bCol);
        *reinterpret_cast<float4*>(&Bs[bRow][bCol]) = bv;
        __syncthreads();

#pragma unroll
        for (int k = 0; k < BK; k++) {
            float ra[TM], rb[TN];
#pragma unroll
            for (int i = 0; i < TM; i++) ra[i] = As[k][trow * TM + i];
#pragma unroll
            for (int j = 0; j < TN; j++) rb[j] = Bs[k][tcol * TN + j];
#pragma unroll
            for (int i = 0; i < TM; i++)
#pragma unroll
                for (int j = 0; j < TN; j++) acc[i][j] += ra[i] * rb[j];
        }
        __syncthreads();
    }

    for (int i = 0; i < TM; i++) {
        int r = bm + trow * TM + i;
        if (r >= M) break;
#pragma unroll
        for (int j = 0; j < TN; j += 4) {
            int cidx = bn + tcol * TN + j;
            float4 v = make_float4(acc[i][j], acc[i][j + 1], acc[i][j + 2], acc[i][j + 3]);
            if (bias) {
                v.x += bias[cidx]; v.y += bias[cidx + 1];
                v.z += bias[cidx + 2]; v.w += bias[cidx + 3];
            }
            *reinterpret_cast<float4*>(C + (long long)r * N + cidx) = v;
        }
    }
}

// -------- aggregation: out[i] = b + h[i]*selfc[i]; then edge scatter --------
__global__ void agg_init_kernel(const float* __restrict__ h, const float* __restrict__ b,
                                float* __restrict__ out) {
    long long i4 = (long long)blockIdx.x * blockDim.x + threadIdx.x;
    long long base = i4 * 4;
    if (base >= (long long)NN * HH) return;
    int node = (int)(base >> 9);
    int f = (int)(base & 511);
    float sc = g_selfc[node];
    float4 hv = *reinterpret_cast<const float4*>(h + base);
    float4 bv = *reinterpret_cast<const float4*>(b + f);
    float4 o;
    o.x = bv.x + hv.x * sc;
    o.y = bv.y + hv.y * sc;
    o.z = bv.z + hv.z * sc;
    o.w = bv.w + hv.w * sc;
    *reinterpret_cast<float4*>(out + base) = o;
}

__global__ void agg_edges_kernel(const float* __restrict__ h,
                                 const int* __restrict__ erow,
                                 const int* __restrict__ ecol,
                                 float* __restrict__ out) {
    long long gid = (long long)blockIdx.x * blockDim.x + threadIdx.x;
    int e = (int)(gid >> 7);        // HH/4 = 128 float4 per edge
    int c4 = (int)(gid & 127);
    if (e >= EE) return;
    int r = erow[e];
    int c = ecol[e];
    float nm = g_norm[e];
    float4 v = *reinterpret_cast<const float4*>(h + (long long)r * HH + c4 * 4);
    float* dst = out + (long long)c * HH + c4 * 4;
    asm volatile("red.global.add.v4.f32 [%0], {%1, %2, %3, %4};"
                 :: "l"(dst), "f"(v.x * nm), "f"(v.y * nm), "f"(v.z * nm), "f"(v.w * nm)
                 : "memory");
}

// -------- batchnorm (training-mode biased stats) --------
__global__ void bn_stats_kernel(const float* __restrict__ X, float* __restrict__ sum,
                                float* __restrict__ sumsq) {
    int f = threadIdx.x;   // 512 threads
    float s = 0.f, s2 = 0.f;
    for (int r = blockIdx.x; r < NN; r += gridDim.x) {
        float v = X[(long long)r * HH + f];
        s += v;
        s2 += v * v;
    }
    atomicAdd(&sum[f], s);
    atomicAdd(&sumsq[f], s2);
}

__global__ void bn_coef_kernel(const float* __restrict__ sum, const float* __restrict__ sumsq,
                               const float* __restrict__ g, const float* __restrict__ beta) {
    int f = threadIdx.x;   // 512 threads, 1 block
    float invN = 1.0f / (float)NN;
    float mu = sum[f] * invN;
    float var = fmaxf(sumsq[f] * invN - mu * mu, 0.0f);
    float s = g[f] * rsqrtf(var + EPS);
    g_bna[f] = s;
    g_bnc[f] = beta[f] - s * mu;
}

__global__ void bn_apply_kernel(const float* __restrict__ X, float* __restrict__ Y) {
    long long i4 = (long long)blockIdx.x * blockDim.x + threadIdx.x;
    long long base = i4 * 4;
    if (base >= (long long)NN * HH) return;
    int f = (int)(base & 511);
    float4 v = *reinterpret_cast<const float4*>(X + base);
    float4 a = *reinterpret_cast<const float4*>(g_bna + f);
    float4 c = *reinterpret_cast<const float4*>(g_bnc + f);
    float4 o;
    o.x = fmaf(a.x, v.x, c.x);
    o.y = fmaf(a.y, v.y, c.y);
    o.z = fmaf(a.z, v.z, c.z);
    o.w = fmaf(a.w, v.w, c.w);
    o.x = o.x > 0.f ? o.x : SLOPE * o.x;
    o.y = o.y > 0.f ? o.y : SLOPE * o.y;
    o.z = o.z > 0.f ? o.z : SLOPE * o.z;
    o.w = o.w > 0.f ? o.w : SLOPE * o.w;
    *reinterpret_cast<float4*>(Y + base) = o;
}

// -------- segment-max pooling via order-preserving uint encode --------
__global__ void pool_kernel(const float* __restrict__ h, const int* __restrict__ batch) {
    long long gid = (long long)blockIdx.x * blockDim.x + threadIdx.x;
    int i = (int)(gid >> 9);
    int f = (int)(gid & 511);
    if (i >= NN) return;
    float v = h[(long long)i * HH + f];
    unsigned u = __float_as_uint(v);
    u = (u & 0x80000000u) ? ~u : (u | 0x80000000u);
    atomicMax(&g_keys[(long long)batch[i] * HH + f], u);
}

__global__ void pool_decode_kernel() {
    long long i = (long long)blockIdx.x * blockDim.x + threadIdx.x;
    if (i >= (long long)GG * HH) return;
    unsigned k = g_keys[i];
    float v;
    if (k == 0u) {
        v = 0.0f;   // empty graph (or -inf) -> 0, matching isfinite fixup
    } else {
        unsigned u = (k & 0x80000000u) ? (k & 0x7fffffffu) : ~k;
        v = __uint_as_float(u);
    }
    g_pooled[i] = v;
}

// -------- host launch --------
extern "C" void kernel_launch(void* const* d_in, const int* in_sizes, int n_in,
                              void* d_out, int out_size) {
    const float* x      = (const float*)d_in[0];
    const int*   ei     = (const int*)d_in[1];    // int32 (JAX x64 disabled)
    const int*   bt     = (const int*)d_in[2];    // int32
    const float* W1     = (const float*)d_in[3];
    const float* b1     = (const float*)d_in[4];
    const float* g1     = (const float*)d_in[5];
    const float* beta1  = (const float*)d_in[6];
    const float* W2     = (const float*)d_in[7];
    const float* b2     = (const float*)d_in[8];
    const float* g2     = (const float*)d_in[9];
    const float* beta2  = (const float*)d_in[10];
    const float* Wf     = (const float*)d_in[11];
    const float* bf     = (const float*)d_in[12];
    float* out = (float*)d_out;

    const int* erow = ei;
    const int* ecol = ei + EE;

    float *buf1, *buf2, *pooled, *stats;
    cudaGetSymbolAddress((void**)&buf1, g_buf1);
    cudaGetSymbolAddress((void**)&buf2, g_buf2);
    cudaGetSymbolAddress((void**)&pooled, g_pooled);
    cudaGetSymbolAddress((void**)&stats, g_stats);

    const int T = 256;
    // precompute
    init_kernel<<<(GG * HH + T - 1) / T, T>>>();
    count_deg_kernel<<<(EE + T - 1) / T, T>>>(ecol);
    dinv_kernel<<<(NN + T - 1) / T, T>>>();
    edge_norm_kernel<<<(EE + T - 1) / T, T>>>(erow, ecol);

    long long elems = (long long)NN * HH;
    int blk_elem4 = (int)((elems / 4 + T - 1) / T);
    int blk_edges = (int)(((long long)EE * 128 + T - 1) / T);
    int blk_pool  = (int)((elems + T - 1) / T);

    // ---- layer 1 ----
    {
        dim3 grid(HH / BN, (NN + BM - 1) / BM);
        sgemm_kernel<<<grid, 256>>>(x, W1, nullptr, buf1, NN, HH, DINF);
    }
    agg_init_kernel<<<blk_elem4, T>>>(buf1, b1, buf2);
    agg_edges_kernel<<<blk_edges, T>>>(buf1, erow, ecol, buf2);
    bn_stats_kernel<<<1024, HH>>>(buf2, stats + 0, stats + HH);
    bn_coef_kernel<<<1, HH>>>(stats + 0, stats + HH, g1, beta1);
    bn_apply_kernel<<<blk_elem4, T>>>(buf2, buf1);

    // ---- layer 2 ----
    {
        dim3 grid(HH / BN, (NN + BM - 1) / BM);
        sgemm_kernel<<<grid, 256>>>(buf1, W2, nullptr, buf2, NN, HH, HH);
    }
    agg_init_kernel<<<blk_elem4, T>>>(buf2, b2, buf1);
    agg_edges_kernel<<<blk_edges, T>>>(buf2, erow, ecol, buf1);
    bn_stats_kernel<<<1024, HH>>>(buf1, stats + 2 * HH, stats + 3 * HH);
    bn_coef_kernel<<<1, HH>>>(stats + 2 * HH, stats + 3 * HH, g2, beta2);
    bn_apply_kernel<<<blk_elem4, T>>>(buf1, buf2);

    // ---- pool + final linear ----
    pool_kernel<<<blk_pool, T>>>(buf2, bt);
    pool_decode_kernel<<<(GG * HH + T - 1) / T, T>>>();
    {
        dim3 grid(OUTC / BN, GG / BM);
        sgemm_kernel<<<grid, 256>>>(pooled, Wf, bf, out, GG, OUTC, HH);
    }
}